// round 4
// baseline (speedup 1.0000x reference)
#include <cuda_runtime.h>
#include <cstdint>

#define IN_CHN  128
#define OUT_CHN 128
#define HW      56
#define PHW     58
#define NB      32
#define NW_TOT  (OUT_CHN*IN_CHN*9)
#define SCALE_F 100.0f

#define TILE_RY 2              // output rows per CTA
#define TILE_N  112            // 2*56 pixels
#define NTILE_Y (HW/TILE_RY)   // 28

// ---- device scratch ----
__device__ int8_t g_acts8[NB * PHW * PHW * IN_CHN];  // 13.8 MB channels-last, zero border
__device__ int8_t g_wt8[9 * OUT_CHN * IN_CHN];       // 147 KB: [tap][o][c]

// smem layout (dynamic): acts 232 rows x 128B = 29696, then 2 weight bufs 16384 each
#define SM_ACT 0
#define SM_W0  29696
#define SM_W1  (29696 + 16384)
#define SM_TOTAL (29696 + 2*16384)   // 62464

#define SWZ(o) ((o) ^ (((o) >> 3) & 0x70))

__device__ __forceinline__ uint32_t smem_u32(const void* p) {
    uint32_t a;
    asm("{ .reg .u64 t; cvta.to.shared.u64 t, %1; cvt.u32.u64 %0, t; }" : "=r"(a) : "l"(p));
    return a;
}
#define CP16(s, g) asm volatile("cp.async.cg.shared.global [%0], [%1], 16;" :: "r"(s), "l"(g))
#define CP_COMMIT() asm volatile("cp.async.commit_group;" ::: "memory")

__device__ __forceinline__ void ldsm_x4(uint32_t* r, uint32_t a) {
    asm volatile("ldmatrix.sync.aligned.m8n8.x4.shared.b16 {%0,%1,%2,%3}, [%4];"
        : "=r"(r[0]), "=r"(r[1]), "=r"(r[2]), "=r"(r[3]) : "r"(a));
}
__device__ __forceinline__ void ldsm_x2(uint32_t* r, uint32_t a) {
    asm volatile("ldmatrix.sync.aligned.m8n8.x2.shared.b16 {%0,%1}, [%2];"
        : "=r"(r[0]), "=r"(r[1]) : "r"(a));
}
__device__ __forceinline__ void imma(int* d, const uint32_t* a, const uint32_t* b) {
    asm volatile("mma.sync.aligned.m16n8k32.row.col.s32.s8.s8.s32 "
        "{%0,%1,%2,%3}, {%4,%5,%6,%7}, {%8,%9}, {%0,%1,%2,%3};"
        : "+r"(d[0]), "+r"(d[1]), "+r"(d[2]), "+r"(d[3])
        : "r"(a[0]), "r"(a[1]), "r"(a[2]), "r"(a[3]), "r"(b[0]), "r"(b[1]));
}

// ============================================================
// Kernel 1: SDP weight synthesis -> sign -> s8 [tap][o][c]
// ============================================================
__global__ void k_weights(const float* __restrict__ M,
                          const float* __restrict__ Z,
                          const float* __restrict__ rv)
{
    int tid  = blockIdx.x * blockDim.x + threadIdx.x;
    int wi   = tid >> 5;
    int lane = tid & 31;
    if (wi >= OUT_CHN * 9 * 4) return;

    int o = wi / 36;
    int r = wi % 36;
    int t = r >> 2;
    int j = r & 3;
    int i = j * 32 + lane;

    int idx = (o * IN_CHN + i) * 9 + t;
    float m = M[idx];
    float z[5];
    float s = 0.f;
#pragma unroll
    for (int k = 0; k < 5; k++) { z[k] = Z[k * NW_TOT + idx]; s += z[k] * z[k]; }
    float inv = rsqrtf(m * m + s / SCALE_F);
    float w = 0.f;
#pragma unroll
    for (int k = 0; k < 5; k++) w += rv[k] * (z[k] * inv);
    w += m * inv;

    g_wt8[(t * OUT_CHN + o) * IN_CHN + i] = (w < 0.f) ? (int8_t)-1 : ((w > 0.f) ? (int8_t)1 : (int8_t)0);
}

// ============================================================
// Kernel 2: binarize acts -> s8 channels-last, zero border
// ============================================================
__global__ void k_pack(const float* __restrict__ x)
{
    int px = threadIdx.x;
    int py = blockIdx.x;
    int b  = blockIdx.y;
    if (px >= PHW) return;

    uint32_t wbuf[32];
#pragma unroll
    for (int k = 0; k < 32; k++) wbuf[k] = 0;

    if (py >= 1 && py <= HW && px >= 1 && px <= HW) {
        const float* xp = x + (size_t)b * IN_CHN * HW * HW + (py - 1) * HW + (px - 1);
#pragma unroll 8
        for (int c4 = 0; c4 < 32; c4++) {
            uint32_t wv = 0;
#pragma unroll
            for (int u = 0; u < 4; u++) {
                float v = xp[(size_t)(c4 * 4 + u) * (HW * HW)];
                uint32_t byte = (v < 0.f) ? 0xFFu : ((v > 0.f) ? 1u : 0u);
                wv |= byte << (u * 8);
            }
            wbuf[c4] = wv;
        }
    }
    uint4* dst = (uint4*)(g_acts8 + ((size_t)(b * PHW + py) * PHW + px) * IN_CHN);
#pragma unroll
    for (int k = 0; k < 8; k++)
        dst[k] = make_uint4(wbuf[4*k], wbuf[4*k+1], wbuf[4*k+2], wbuf[4*k+3]);
}

// ============================================================
// Kernel 3: s8 implicit-GEMM conv via mma.sync.m16n8k32
// CTA: (b, 2 out rows). 8 warps; warp w = o-rows [w*16, w*16+16) x 112 px.
// ============================================================
__global__ void __launch_bounds__(256, 2)
k_conv(const float* __restrict__ Alpha, float* __restrict__ out)
{
    extern __shared__ char smem[];
    uint32_t sbase = smem_u32(smem);
    int tid = threadIdx.x;
    int wid = tid >> 5;
    int lid = tid & 31;
    int b   = blockIdx.y;
    int y0  = blockIdx.x * TILE_RY;   // output row base == padded row base of halo

    // ---- prologue: stage activations (29.7KB) + weight tap0, then tap1 ----
    const char* actG = (const char*)g_acts8 + ((size_t)(b * PHW + y0) * PHW) * IN_CHN;
    for (int i = tid; i < 1856; i += 256) CP16(sbase + SM_ACT + SWZ(i * 16), actG + i * 16);
    {
        const char* wg = (const char*)g_wt8;
        for (int i = tid; i < 1024; i += 256) CP16(sbase + SM_W0 + SWZ(i * 16), wg + i * 16);
    }
    CP_COMMIT();
    {
        const char* wg = (const char*)g_wt8 + 16384;
        for (int i = tid; i < 1024; i += 256) CP16(sbase + SM_W1 + SWZ(i * 16), wg + i * 16);
    }
    CP_COMMIT();

    int acc[14][4];
#pragma unroll
    for (int j = 0; j < 14; j++) { acc[j][0] = acc[j][1] = acc[j][2] = acc[j][3] = 0; }

    // ldmatrix A address lane mapping (x4): orow = w*16 + (lane&15), kseg16 = (lane>=16)
    int a_orow = wid * 16 + (lid & 15);
    int a_koff = (lid >= 16) ? 16 : 0;
    // ldmatrix B address lane mapping (x2): px lane = lane&7, kseg16 = ((lane&15)>=8)
    int b_lane = lid & 7;
    int b_koff = ((lid & 15) >= 8) ? 16 : 0;

#pragma unroll 1
    for (int t = 0; t < 9; t++) {
        if (t == 8) { asm volatile("cp.async.wait_group 0;" ::: "memory"); }
        else        { asm volatile("cp.async.wait_group 1;" ::: "memory"); }
        __syncthreads();

        int dy = t / 3, dx = t % 3;
        uint32_t wS = sbase + ((t & 1) ? SM_W1 : SM_W0);

        // load A fragments for all 4 k-steps (weights for this tap)
        uint32_t aM[4][4];
#pragma unroll
        for (int ks = 0; ks < 4; ks++)
            ldsm_x4(aM[ks], wS + SWZ(a_orow * 128 + ks * 32 + a_koff));

        int dyx = dy * PHW + dx;
#pragma unroll
        for (int j = 0; j < 14; j++) {
            int px = j * 8 + b_lane;
            int yo = (px >= 56) ? 1 : 0;
            int xo = px - (yo ? 56 : 0);
            int ri = (yo) * PHW + xo + dyx;
            uint32_t bbase = sbase + SM_ACT;
#pragma unroll
            for (int ks = 0; ks < 4; ks++) {
                uint32_t bf[2];
                ldsm_x2(bf, bbase + SWZ(ri * 128 + ks * 32 + b_koff));
                imma(acc[j], aM[ks], bf);
            }
        }
        __syncthreads();
        if (t + 2 <= 8) {
            const char* wg = (const char*)g_wt8 + (size_t)(t + 2) * 16384;
            uint32_t dstS = sbase + ((t & 1) ? SM_W1 : SM_W0);
            for (int i = tid; i < 1024; i += 256) CP16(dstS + SWZ(i * 16), wg + i * 16);
            CP_COMMIT();
        }
    }

    // ---- epilogue: alpha scale + direct float2 stores ----
    int qrow = lid >> 2;
    int qcol = (lid & 3) * 2;
    int o0 = wid * 16 + qrow;
    float al0 = Alpha[o0];
    float al1 = Alpha[o0 + 8];
    size_t ob = (size_t)b * OUT_CHN * (HW * HW);
    float* p0base = out + ob + (size_t)o0 * (HW * HW) + (size_t)y0 * HW;

#pragma unroll
    for (int j = 0; j < 14; j++) {
        int px = j * 8 + qcol;
        int yo = (px >= 56) ? 1 : 0;
        int xo = px - (yo ? 56 : 0);
        float* p0 = p0base + yo * HW + xo;
        float2 v0; v0.x = al0 * (float)acc[j][0]; v0.y = al0 * (float)acc[j][1];
        *(float2*)p0 = v0;
        float2 v1; v1.x = al1 * (float)acc[j][2]; v1.y = al1 * (float)acc[j][3];
        *(float2*)(p0 + 8 * (HW * HW)) = v1;
    }
}

// ============================================================
extern "C" void kernel_launch(void* const* d_in, const int* in_sizes, int n_in,
                              void* d_out, int out_size)
{
    const float* x     = (const float*)d_in[0];
    const float* Alpha = (const float*)d_in[1];
    const float* M     = (const float*)d_in[2];
    const float* Z     = (const float*)d_in[3];
    const float* rv    = (const float*)d_in[4];
    float* out = (float*)d_out;

    cudaFuncSetAttribute(k_conv, cudaFuncAttributeMaxDynamicSharedMemorySize, SM_TOTAL);

    k_weights<<<576, 256>>>(M, Z, rv);
    k_pack<<<dim3(PHW, NB), 64>>>(x);
    k_conv<<<dim3(NTILE_Y, NB), 256, SM_TOTAL>>>(Alpha, out);
}

// round 5
// speedup vs baseline: 2.3476x; 2.3476x over previous
#include <cuda_runtime.h>
#include <cstdint>

#define IN_CHN  128
#define OUT_CHN 128
#define HW      56
#define PHW     58
#define NB      32
#define NW_TOT  (OUT_CHN*IN_CHN*9)
#define SCALE_F 100.0f

// ---- device scratch ----
__device__ uint4 g_abits[NB * PHW * PHW];     // sign bits (1 = x<0)
__device__ uint4 g_vbits[NB * PHW * PHW];     // validity bits (1 = x!=0)
__device__ uint4 g_wbits[OUT_CHN * 9];        // weight sign bits [o][tap]

#define PACK_BLOCKS (NB * PHW)                // 1856
#define WB_BLOCKS   576

// ============================================================
// Fused prep kernel: block < PACK_BLOCKS -> activation pack,
// else -> SDP weight synthesis + sign pack.
// ============================================================
__global__ void __launch_bounds__(256)
k_prep(const float* __restrict__ x,
       const float* __restrict__ M,
       const float* __restrict__ Z,
       const float* __restrict__ rv)
{
    int bid = blockIdx.x;
    int tid = threadIdx.x;

    if (bid < PACK_BLOCKS) {
        // ---- activation pack: 4 threads per pixel (32 channels each) ----
        int b  = bid / PHW;
        int py = bid % PHW;
        int px = tid & 63;
        int q  = tid >> 6;          // channel quarter 0..3
        if (px >= PHW) return;

        uint32_t aw = 0, vw = 0;
        if (py >= 1 && py <= HW && px >= 1 && px <= HW) {
            const float* xp = x + (size_t)b * IN_CHN * HW * HW
                                + (size_t)(q * 32) * (HW * HW)
                                + (py - 1) * HW + (px - 1);
#pragma unroll 8
            for (int c = 0; c < 32; c++) {
                float val = xp[(size_t)c * (HW * HW)];
                aw |= (val < 0.f)  ? (1u << c) : 0u;
                vw |= (val != 0.f) ? (1u << c) : 0u;
            }
        }
        int pidx = (b * PHW + py) * PHW + px;
        ((uint32_t*)g_abits)[pidx * 4 + q] = aw;
        ((uint32_t*)g_vbits)[pidx * 4 + q] = vw;
    } else {
        // ---- weight synthesis ----
        int gtid = (bid - PACK_BLOCKS) * 256 + tid;
        int wi   = gtid >> 5;
        int lane = gtid & 31;
        if (wi >= OUT_CHN * 9 * 4) return;

        int o = wi / 36;
        int r = wi % 36;
        int t = r >> 2;
        int j = r & 3;
        int i = j * 32 + lane;

        int idx = (o * IN_CHN + i) * 9 + t;
        float m = M[idx];
        float z[5];
        float s = 0.f;
#pragma unroll
        for (int k = 0; k < 5; k++) { z[k] = Z[k * NW_TOT + idx]; s += z[k] * z[k]; }
        float inv = rsqrtf(m * m + s / SCALE_F);
        float w = 0.f;
#pragma unroll
        for (int k = 0; k < 5; k++) w += rv[k] * (z[k] * inv);
        w += m * inv;

        unsigned bits = __ballot_sync(0xFFFFFFFFu, w < 0.f);
        if (lane == 0) ((uint32_t*)g_wbits)[wi] = bits;
    }
}

// ============================================================
// Conv: XNOR-popcount with carry-save (full-adder) compression.
// CTA = (y, b). 224 threads: strip = tid%28 (2 out px),
// og = tid/28 (8 groups x 16 o). Per o: taps grouped in triples;
// FA compresses 3 term-words -> (sum, carry): POPC 72 -> 48.
// ============================================================
__global__ void __launch_bounds__(224, 2)
k_conv(const float* __restrict__ Alpha, float* __restrict__ out)
{
    __shared__ uint4 wsm[OUT_CHN * 9];
    __shared__ float alsm[OUT_CHN];

    int tid = threadIdx.x;
    int y   = blockIdx.x;
    int b   = blockIdx.y;

    for (int k = tid; k < OUT_CHN * 9; k += 224) wsm[k] = g_wbits[k];
    if (tid < OUT_CHN) alsm[tid] = Alpha[tid];
    __syncthreads();

    int xp = tid % 28;
    int og = tid / 28;
    int x0 = xp * 2;

    uint32_t a[3][4][4], v[3][4][4];
    int vsum0 = 0, vsum1 = 0;
#pragma unroll
    for (int r = 0; r < 3; r++) {
#pragma unroll
        for (int c = 0; c < 4; c++) {
            int pidx = (b * PHW + (y + r)) * PHW + (x0 + c);
            uint4 ua = g_abits[pidx];
            uint4 uv = g_vbits[pidx];
            a[r][c][0] = ua.x; a[r][c][1] = ua.y; a[r][c][2] = ua.z; a[r][c][3] = ua.w;
            v[r][c][0] = uv.x; v[r][c][1] = uv.y; v[r][c][2] = uv.z; v[r][c][3] = uv.w;
            int pv = __popc(uv.x) + __popc(uv.y) + __popc(uv.z) + __popc(uv.w);
            if (c < 3) vsum0 += pv;
            if (c > 0) vsum1 += pv;
        }
    }

    float* outp = out + ((size_t)b * OUT_CHN) * (HW * HW) + y * HW + x0;

#pragma unroll 1
    for (int oi = 0; oi < 16; oi++) {
        int o = og * 16 + oi;
        const uint4* wrow = &wsm[o * 9];

        int s0 = 0, c0 = 0;   // pixel0: weight-1 / weight-2 popc sums
        int s1 = 0, c1 = 0;   // pixel1
#pragma unroll
        for (int rg = 0; rg < 3; rg++) {
            uint32_t w0[4], w1[4], w2[4];
            *(uint4*)w0 = wrow[rg * 3 + 0];
            *(uint4*)w1 = wrow[rg * 3 + 1];
            *(uint4*)w2 = wrow[rg * 3 + 2];
#pragma unroll
            for (int j = 0; j < 4; j++) {
                // pixel 0: taps use cols rg rows, cols 0,1,2
                uint32_t t0 = (a[rg][0][j] ^ w0[j]) & v[rg][0][j];
                uint32_t t1 = (a[rg][1][j] ^ w1[j]) & v[rg][1][j];
                uint32_t t2 = (a[rg][2][j] ^ w2[j]) & v[rg][2][j];
                uint32_t xs = t0 ^ t1 ^ t2;
                uint32_t xc = (t0 & t1) | ((t0 ^ t1) & t2);
                s0 += __popc(xs);
                c0 += __popc(xc);
                // pixel 1: cols 1,2,3
                uint32_t u0 = (a[rg][1][j] ^ w0[j]) & v[rg][1][j];
                uint32_t u1 = (a[rg][2][j] ^ w1[j]) & v[rg][2][j];
                uint32_t u2 = (a[rg][3][j] ^ w2[j]) & v[rg][3][j];
                uint32_t ys = u0 ^ u1 ^ u2;
                uint32_t yc = (u0 & u1) | ((u0 ^ u1) & u2);
                s1 += __popc(ys);
                c1 += __popc(yc);
            }
        }
        int acc0 = s0 + 2 * c0;
        int acc1 = s1 + 2 * c1;
        float al = alsm[o];
        float2 res;
        res.x = al * (float)(vsum0 - 2 * acc0);
        res.y = al * (float)(vsum1 - 2 * acc1);
        *(float2*)(outp + (size_t)o * (HW * HW)) = res;
    }
}

// ============================================================
extern "C" void kernel_launch(void* const* d_in, const int* in_sizes, int n_in,
                              void* d_out, int out_size)
{
    const float* x     = (const float*)d_in[0];
    const float* Alpha = (const float*)d_in[1];
    const float* M     = (const float*)d_in[2];
    const float* Z     = (const float*)d_in[3];
    const float* rv    = (const float*)d_in[4];
    float* out = (float*)d_out;

    k_prep<<<PACK_BLOCKS + WB_BLOCKS, 256>>>(x, M, Z, rv);
    k_conv<<<dim3(HW, NB), 224>>>(Alpha, out);
}